// round 17
// baseline (speedup 1.0000x reference)
#include <cuda_runtime.h>
#include <cuda_bf16.h>
#include <cstdint>

#define NROWS 8192
#define DDIM  256
#define TM    128
#define TN    128
#define KCH   32            // K chunk in bf16 elems = 64 bytes/row
#define NBLK  (NROWS / TM)
#define NTILES (NBLK * (NBLK + 1) / 2)   // 2080 upper-triangular tiles
#define NHALF  (NTILES / 2)              // 1040 CTAs, 2 tiles each

// Scratch (no cudaMalloc allowed).
__device__ __nv_bfloat16 g_Y[NROWS * DDIM];
__device__ float  g_tot[NROWS];
__device__ float  g_pos[NROWS];
__device__ double g_loss_acc;
__device__ int    g_loss_cnt;

// SMEM per buffer: A 8K | B 8K = 16KB; 3 buffers = 48KB.
#define OFF_A  0
#define OFF_B  8192
#define BUF_SZ 16384
#define NSTAGE 3
#define DSMEM_TOTAL (NSTAGE * BUF_SZ + 128)

// ---------------------------------------------------------------------------
__device__ __forceinline__ uint32_t smem_u32(const void* p) {
    uint32_t a;
    asm("{ .reg .u64 t; cvta.to.shared.u64 t, %1; cvt.u32.u64 %0, t; }" : "=r"(a) : "l"(p));
    return a;
}
__device__ __forceinline__ void cpa16(uint32_t dst, const void* src) {
    asm volatile("cp.async.cg.shared.global [%0], [%1], 16;" :: "r"(dst), "l"(src));
}
#define CPA_COMMIT() asm volatile("cp.async.commit_group;" ::: "memory")

__device__ __forceinline__ void ldsm4(uint32_t* d, uint32_t addr) {
    asm volatile("ldmatrix.sync.aligned.m8n8.x4.shared.b16 {%0,%1,%2,%3}, [%4];"
                 : "=r"(d[0]), "=r"(d[1]), "=r"(d[2]), "=r"(d[3]) : "r"(addr));
}
__device__ __forceinline__ void mma16816(float* c, const uint32_t* a, const uint32_t* b) {
    asm volatile("mma.sync.aligned.m16n8k16.row.col.f32.bf16.bf16.f32 "
                 "{%0,%1,%2,%3}, {%4,%5,%6,%7}, {%8,%9}, {%0,%1,%2,%3};"
                 : "+f"(c[0]), "+f"(c[1]), "+f"(c[2]), "+f"(c[3])
                 : "r"(a[0]), "r"(a[1]), "r"(a[2]), "r"(a[3]), "r"(b[0]), "r"(b[1]));
}

// 64B-row swizzle: unit x = u ^ ((r>>1)&3); (r%2, x) distinct across 8 rows.
__device__ __forceinline__ uint32_t dof64(int r, int u) {
    return (uint32_t)(r * 64 + ((u ^ ((r >> 1) & 3)) << 4));
}

// exp2 on the FMA pipe: float-bias range reduction + degree-5 Taylor on [-0.5,0.5].
__device__ __forceinline__ float fexp2(float s) {
    float z = s + 12582912.0f;
    float f = s - (z - 12582912.0f);
    int   k = __float_as_int(z) << 23;
    float p =             1.3333558e-3f;
    p = fmaf(p, f, 9.6181291e-3f);
    p = fmaf(p, f, 5.5504109e-2f);
    p = fmaf(p, f, 2.4022651e-1f);
    p = fmaf(p, f, 6.9314718e-1f);
    p = fmaf(p, f, 1.0f);
    return __int_as_float(__float_as_int(p) + k);
}

// tile k -> (bi <= bj)
__device__ __forceinline__ void tri_decode(int k, int& bi, int& bj) {
    int b = (int)((2.0 * NBLK + 1.0
                   - sqrt((2.0 * NBLK + 1.0) * (2.0 * NBLK + 1.0) - 8.0 * (double)k)) * 0.5);
    while (b > 0 && b * NBLK - b * (b - 1) / 2 > k) b--;
    while ((b + 1) * NBLK - (b + 1) * b / 2 <= k) b++;
    bi = b;
    bj = b + (k - (b * NBLK - b * (b - 1) / 2));
}

// ---------------------------------------------------------------------------
// Kernel 1: normalize rows -> bf16; zero accumulators + loss scalar state.
// ---------------------------------------------------------------------------
__global__ void norm_kernel(const float* __restrict__ X) {
    if (blockIdx.x == 0 && threadIdx.x == 0) { g_loss_acc = 0.0; g_loss_cnt = 0; }
    int row  = blockIdx.x * 8 + (threadIdx.x >> 5);
    int lane = threadIdx.x & 31;
    const float4* x4 = reinterpret_cast<const float4*>(X + row * DDIM);
    float4 v1 = x4[lane];
    float4 v2 = x4[lane + 32];
    float ss = v1.x*v1.x + v1.y*v1.y + v1.z*v1.z + v1.w*v1.w
             + v2.x*v2.x + v2.y*v2.y + v2.z*v2.z + v2.w*v2.w;
    #pragma unroll
    for (int o = 16; o > 0; o >>= 1) ss += __shfl_xor_sync(0xffffffffu, ss, o);
    float r = rsqrtf(ss);
    float vs[8] = {v1.x*r, v1.y*r, v1.z*r, v1.w*r, v2.x*r, v2.y*r, v2.z*r, v2.w*r};

    __nv_bfloat162* yh = reinterpret_cast<__nv_bfloat162*>(g_Y + row * DDIM);
    #pragma unroll
    for (int p = 0; p < 4; p++) {
        __nv_bfloat162 h = __floats2bfloat162_rn(vs[p * 2], vs[p * 2 + 1]);
        int base = (p < 2) ? (lane * 2 + p) : ((lane + 32) * 2 + (p - 2));
        yh[base] = h;
    }
    if (lane == 0) { g_tot[row] = 0.0f; g_pos[row] = 0.0f; }
}

// ---------------------------------------------------------------------------
// Kernel 2: single-term bf16 HMMA GEMM, 2 tiles per CTA; tile-2 chunk-0/1
// prefetch issued BEFORE tile-1's epilogue so exp/reduce overlaps the loads.
// ---------------------------------------------------------------------------
__global__ __launch_bounds__(256, 2)
void gemm_mma_kernel(const int* __restrict__ labels, const float* __restrict__ tptr) {
    extern __shared__ char dsm_raw[];

    const int tid  = threadIdx.x;
    const int wid  = tid >> 5;
    const int lane = tid & 31;
    const uint32_t sbase = (smem_u32(dsm_raw) + 127u) & ~127u;

    const float esc = 1.442695041f / (*tptr);
    const float eself = fexp2(esc);          // exact exp(1/t): cos_ii == 1
    const int wm = wid & 1, wn = wid >> 1;
    const int sub = lane >> 3, l7 = lane & 7;
    const int q = lane & 3, g = lane >> 2;

    const char* yP = (const char*)g_Y;

    auto load_chunk = [&](int bufidx, int kc, int r0, int c0) {
        uint32_t b = sbase + bufidx * BUF_SZ;
        #pragma unroll
        for (int i = 0; i < 4; i++) {
            int idx = tid + i * 256;
            int arr = idx >> 9;              // 0:A 1:B
            int r   = (idx >> 2) & 127;
            int u   = idx & 3;
            uint32_t dof = dof64(r, u) + arr * OFF_B;
            int grow = (arr ? c0 : r0) + r;
            cpa16(b + dof, yP + (size_t)grow * (DDIM * 2) + kc * 64 + u * 16);
        }
    };

    int bi, bj;
    tri_decode(blockIdx.x, bi, bj);
    int row0 = bi * TM, col0 = bj * TN;
    bool offdiag = (bi != bj);

    int buf = 0;
    load_chunk(0, 0, row0, col0);
    CPA_COMMIT();
    load_chunk(1, 1, row0, col0);
    CPA_COMMIT();

    const int NCH = DDIM / KCH;  // 8

    #pragma unroll 1
    for (int half = 0; half < 2; half++) {
        float acc[4][4][4];
        #pragma unroll
        for (int m = 0; m < 4; m++)
            #pragma unroll
            for (int n = 0; n < 4; n++)
                #pragma unroll
                for (int j = 0; j < 4; j++) acc[m][n][j] = 0.0f;

        int cb = buf;
        #pragma unroll 1
        for (int kc = 0; kc < NCH; kc++) {
            if (kc < NCH - 1) {
                asm volatile("cp.async.wait_group 1;" ::: "memory");
            } else {
                asm volatile("cp.async.wait_group 0;" ::: "memory");
            }
            __syncthreads();

            if (kc + 2 < NCH) {
                load_chunk((cb + 2) % NSTAGE, kc + 2, row0, col0);
                CPA_COMMIT();
            }

            const uint32_t b = sbase + cb * BUF_SZ;
            #pragma unroll
            for (int ks = 0; ks < 2; ks++) {
                uint32_t ah[4][4], bh[2][4];
                #pragma unroll
                for (int ma = 0; ma < 4; ma++) {
                    int mr = wm * 64 + ma * 16 + ((sub & 1) << 3) + l7;
                    int u  = 2 * ks + (sub >> 1);
                    ldsm4(ah[ma], b + OFF_A + dof64(mr, u));
                }
                #pragma unroll
                for (int nb = 0; nb < 2; nb++) {
                    int nr = wn * 32 + nb * 16 + ((sub >> 1) << 3) + l7;
                    int u  = 2 * ks + (sub & 1);
                    ldsm4(bh[nb], b + OFF_B + dof64(nr, u));
                }
                #pragma unroll
                for (int ma = 0; ma < 4; ma++)
                    #pragma unroll
                    for (int na = 0; na < 4; na++)
                        mma16816(acc[ma][na], ah[ma], &bh[na >> 1][(na & 1) * 2]);
            }
            cb = (cb + 1) % NSTAGE;
        }
        buf = cb;   // advanced by 8 == +2 mod 3

        // ---- before epilogue: prefetch next tile's first two chunks ----
        // Safe: buffers (buf) and (buf+1)%3 held chunks 5 and 6, whose reads
        // are fenced by the kc=7 barrier every thread has passed.
        int nrow0 = 0, ncol0 = 0;
        bool noffd = false;
        if (half == 0) {
            int nbi, nbj;
            tri_decode(blockIdx.x + NHALF, nbi, nbj);
            nrow0 = nbi * TM; ncol0 = nbj * TN; noffd = (nbi != nbj);
            load_chunk(buf, 0, nrow0, ncol0);
            CPA_COMMIT();
            load_chunk((buf + 1) % NSTAGE, 1, nrow0, ncol0);
            CPA_COMMIT();
        }

        // ---- Epilogue (registers + L1-cached label reads; overlaps loads) --
        int cl_[4][2];
        #pragma unroll
        for (int na = 0; na < 4; na++) {
            int cbse = col0 + wn * 32 + na * 8 + q * 2;
            cl_[na][0] = __ldg(&labels[cbse]);
            cl_[na][1] = __ldg(&labels[cbse + 1]);
        }

        float ct[4][2], cp[4][2];
        #pragma unroll
        for (int na = 0; na < 4; na++) { ct[na][0] = ct[na][1] = cp[na][0] = cp[na][1] = 0.f; }

        #pragma unroll
        for (int ma = 0; ma < 4; ma++) {
            int rA = row0 + wm * 64 + ma * 16 + g;
            int rB = rA + 8;
            int lA = __ldg(&labels[rA]), lB = __ldg(&labels[rB]);
            float tsA = 0.f, psA = 0.f, tsB = 0.f, psB = 0.f;
            #pragma unroll
            for (int na = 0; na < 4; na++) {
                float e0 = fexp2(acc[ma][na][0] * esc);
                float e1 = fexp2(acc[ma][na][1] * esc);
                float e2 = fexp2(acc[ma][na][2] * esc);
                float e3 = fexp2(acc[ma][na][3] * esc);
                if (!offdiag) {              // patch exact self-pairs
                    int c0i = col0 + wn * 32 + na * 8 + q * 2;
                    if (c0i     == rA) e0 = eself;
                    if (c0i + 1 == rA) e1 = eself;
                    if (c0i     == rB) e2 = eself;
                    if (c0i + 1 == rB) e3 = eself;
                }
                bool m0 = (lA == cl_[na][0]), m1 = (lA == cl_[na][1]);
                bool m2 = (lB == cl_[na][0]), m3 = (lB == cl_[na][1]);
                tsA += e0 + e1;
                tsB += e2 + e3;
                psA += (m0 ? e0 : 1.0f) + (m1 ? e1 : 1.0f);
                psB += (m2 ? e2 : 1.0f) + (m3 ? e3 : 1.0f);
                if (offdiag) {
                    ct[na][0] += e0 + e2;
                    ct[na][1] += e1 + e3;
                    cp[na][0] += (m0 ? e0 : 1.0f) + (m2 ? e2 : 1.0f);
                    cp[na][1] += (m1 ? e1 : 1.0f) + (m3 ? e3 : 1.0f);
                }
            }
            #pragma unroll
            for (int o = 1; o <= 2; o <<= 1) {
                tsA += __shfl_xor_sync(0xffffffffu, tsA, o);
                psA += __shfl_xor_sync(0xffffffffu, psA, o);
                tsB += __shfl_xor_sync(0xffffffffu, tsB, o);
                psB += __shfl_xor_sync(0xffffffffu, psB, o);
            }
            if (q == 0) {
                atomicAdd(&g_tot[rA], tsA);
                atomicAdd(&g_pos[rA], psA);
                atomicAdd(&g_tot[rB], tsB);
                atomicAdd(&g_pos[rB], psB);
            }
        }

        if (offdiag) {
            #pragma unroll
            for (int na = 0; na < 4; na++)
                #pragma unroll
                for (int bb = 0; bb < 2; bb++) {
                    float t = ct[na][bb], p = cp[na][bb];
                    #pragma unroll
                    for (int o = 4; o <= 16; o <<= 1) {
                        t += __shfl_xor_sync(0xffffffffu, t, o);
                        p += __shfl_xor_sync(0xffffffffu, p, o);
                    }
                    if (g == 0) {
                        int col = col0 + wn * 32 + na * 8 + q * 2 + bb;
                        atomicAdd(&g_tot[col], t);
                        atomicAdd(&g_pos[col], p);
                    }
                }
        }

        row0 = nrow0; col0 = ncol0; offdiag = noffd;
    }
}

// ---------------------------------------------------------------------------
// Kernel 3: loss in ONE launch. 32 blocks; each adds its partial to a global
// double; the last-arriving block writes out = acc / N.
// ---------------------------------------------------------------------------
__global__ void loss_kernel(float* __restrict__ out) {
    __shared__ double sd[256];
    int r = blockIdx.x * 256 + threadIdx.x;
    float p  = g_pos[r];
    float ng = g_tot[r] + (float)NROWS - p;
    sd[threadIdx.x] = (double)(logf(ng) - logf(p));
    __syncthreads();
    #pragma unroll
    for (int o = 128; o > 0; o >>= 1) {
        if (threadIdx.x < o) sd[threadIdx.x] += sd[threadIdx.x + o];
        __syncthreads();
    }
    if (threadIdx.x == 0) {
        atomicAdd(&g_loss_acc, sd[0]);
        __threadfence();
        int done = atomicAdd(&g_loss_cnt, 1);
        if (done == 31) out[0] = (float)(g_loss_acc / (double)NROWS);
    }
}

// ---------------------------------------------------------------------------
extern "C" void kernel_launch(void* const* d_in, const int* in_sizes, int n_in,
                              void* d_out, int out_size) {
    const float* X   = (const float*)d_in[0];
    const int*   lab = (const int*)d_in[1];
    const float* t   = (const float*)d_in[2];
    float*       out = (float*)d_out;

    cudaFuncSetAttribute(gemm_mma_kernel, cudaFuncAttributeMaxDynamicSharedMemorySize,
                         DSMEM_TOTAL);

    norm_kernel<<<NROWS / 8, 256>>>(X);
    gemm_mma_kernel<<<NHALF, 256, DSMEM_TOTAL>>>(lab, t);
    loss_kernel<<<32, 256>>>(out);
}